// round 5
// baseline (speedup 1.0000x reference)
#include <cuda_runtime.h>
#include <cuda_bf16.h>
#include <cstdint>
#include <cstddef>

// ---------------- problem constants ----------------
#define B_ROWS 4096
#define C_ROWS 65536
#define DIM    1024
#define TOPK   5

// ---------------- GEMM tiling (int8 mma.sync) ----------------
#define BM 128
#define BN 256
#define BK 128                  // int8 elements per stage (128 B rows -> SW128)
#define NS 3                    // cp.async stages
#define NKI (DIM / BK)          // 8
#define NTILES (C_ROWS / BN)    // 256
#define CAND_PER_TILE 8
#define CAND_PER_ROW (NTILES * CAND_PER_TILE)  // 2048
#define RESCORE 32

#define A_BYTES (BM * BK)                  // 16384
#define B_BYTES (BN * BK)                  // 32768
#define STAGE_BYTES (A_BYTES + B_BYTES)    // 49152
#define CS_STRIDE 260
#define SB_OFF (NS * STAGE_BYTES)          // sb cache after the stage ring
#define SMEM_BYTES (NS * STAGE_BYTES + 1024)

// SW128 swizzle (Swizzle<3,4,3>)
#define SWZ(o) ((o) ^ (((o) >> 3) & 0x70))

// ---------------- device scratch ----------------
__device__ __align__(16) uint8_t g_memq[(size_t)C_ROWS * DIM]; // per-row-scaled int8
__device__ __align__(16) uint8_t g_xq[(size_t)B_ROWS * DIM];   // per-row-scaled int8
__device__ float g_minv[C_ROWS];   // 1/||mem_row||  (for exact rescore)
__device__ float g_xinv[B_ROWS];   // 1/||x_row||
__device__ float g_msb[C_ROWS];    // descale: rowmax_norm/127 (memory)
__device__ __align__(16) float g_cv[(size_t)B_ROWS * CAND_PER_ROW];
__device__ __align__(16) int   g_ci[(size_t)B_ROWS * CAND_PER_ROW];

// ---------------- PTX helpers ----------------
__device__ __forceinline__ void cp16(uint32_t saddr, const void* gaddr) {
    asm volatile("cp.async.cg.shared.global [%0], [%1], 16;" :: "r"(saddr), "l"(gaddr));
}
__device__ __forceinline__ void cp_commit() {
    asm volatile("cp.async.commit_group;" ::: "memory");
}
__device__ __forceinline__ void ldsm4(uint32_t (&r)[4], uint32_t addr) {
    asm volatile("ldmatrix.sync.aligned.m8n8.x4.shared.b16 {%0,%1,%2,%3}, [%4];"
                 : "=r"(r[0]), "=r"(r[1]), "=r"(r[2]), "=r"(r[3]) : "r"(addr));
}
// int8 IMMA: D[16x8](s32) += A[16x32](s8) * B[32x8](s8)
__device__ __forceinline__ void mma_s8(int (&c)[4], const uint32_t (&a)[4],
                                       uint32_t b0, uint32_t b1) {
    asm volatile(
        "mma.sync.aligned.m16n8k32.row.col.s32.s8.s8.s32 "
        "{%0,%1,%2,%3},{%4,%5,%6,%7},{%8,%9},{%0,%1,%2,%3};"
        : "+r"(c[0]), "+r"(c[1]), "+r"(c[2]), "+r"(c[3])
        : "r"(a[0]), "r"(a[1]), "r"(a[2]), "r"(a[3]), "r"(b0), "r"(b1));
}

// ---------------- prep: normalize + per-row-max int8 quantization ----------------
__device__ __forceinline__ void prep_row_q8(const float* __restrict__ src,
                                            uint8_t* __restrict__ dst,
                                            float* __restrict__ inv,
                                            float* __restrict__ sb) {
    int row = blockIdx.x;
    const float4* s4 = reinterpret_cast<const float4*>(src + (size_t)row * DIM);
    float4 v = s4[threadIdx.x];
    float ss = v.x * v.x + v.y * v.y + v.z * v.z + v.w * v.w;
    #pragma unroll
    for (int o = 16; o; o >>= 1) ss += __shfl_down_sync(0xffffffffu, ss, o);
    __shared__ float wred[8];
    __shared__ float s_inv, s_scl;
    if ((threadIdx.x & 31) == 0) wred[threadIdx.x >> 5] = ss;
    __syncthreads();
    if (threadIdx.x == 0) {
        float t = 0.f;
        #pragma unroll
        for (int i = 0; i < 8; i++) t += wred[i];
        float iv = 1.0f / fmaxf(sqrtf(t), 1e-12f);
        inv[row] = iv;
        s_inv = iv;
    }
    __syncthreads();
    float iv = s_inv;
    float am = fmaxf(fmaxf(fabsf(v.x), fabsf(v.y)), fmaxf(fabsf(v.z), fabsf(v.w))) * iv;
    #pragma unroll
    for (int o = 16; o; o >>= 1) am = fmaxf(am, __shfl_down_sync(0xffffffffu, am, o));
    if ((threadIdx.x & 31) == 0) wred[threadIdx.x >> 5] = am;
    __syncthreads();
    if (threadIdx.x == 0) {
        float m = 0.f;
        #pragma unroll
        for (int i = 0; i < 8; i++) m = fmaxf(m, wred[i]);
        m = fmaxf(m, 1e-12f);
        sb[row] = m * (1.0f / 127.0f);
        s_scl = 127.0f / m;
    }
    __syncthreads();
    float sc = iv * s_scl;
    int qx = __float2int_rn(v.x * sc), qy = __float2int_rn(v.y * sc);
    int qz = __float2int_rn(v.z * sc), qw = __float2int_rn(v.w * sc);
    uint32_t wq = (uint32_t)(qx & 0xff) | ((uint32_t)(qy & 0xff) << 8) |
                  ((uint32_t)(qz & 0xff) << 16) | ((uint32_t)(qw & 0xff) << 24);
    reinterpret_cast<uint32_t*>(dst)[(size_t)row * (DIM / 4) + threadIdx.x] = wq;
}
__device__ float g_xsb_dummy[B_ROWS];  // x descale unused for ranking
__global__ void prep_mem_kernel(const float* __restrict__ src) {
    prep_row_q8(src, g_memq, g_minv, g_msb);
}
__global__ void prep_x_kernel(const float* __restrict__ src) {
    prep_row_q8(src, g_xq, g_xinv, g_xsb_dummy);
}

// ---------------- coarse int8 GEMM + per-tile top-8 ----------------
__device__ __forceinline__ void fill_stage(uint32_t su, int bm, int bn, int buf,
                                           int kc, int tid) {
    uint32_t base = su + buf * STAGE_BYTES;
    const uint8_t* gA = g_xq   + (size_t)(bm * BM) * DIM + kc * BK;
    const uint8_t* gB = g_memq + (size_t)(bn * BN) * DIM + kc * BK;
    #pragma unroll
    for (int i = 0; i < 4; i++) {
        int c = i * 256 + tid;
        int row = c >> 3, off = c & 7;
        uint32_t bo = (uint32_t)(row * BK + off * 16);
        cp16(base + SWZ(bo), gA + (size_t)row * DIM + off * 16);
    }
    #pragma unroll
    for (int i = 0; i < 8; i++) {
        int c = i * 256 + tid;
        int row = c >> 3, off = c & 7;
        uint32_t bo = (uint32_t)(row * BK + off * 16);
        cp16(base + A_BYTES + SWZ(bo), gB + (size_t)row * DIM + off * 16);
    }
    cp_commit();
}

__global__ __launch_bounds__(256, 1) void gemm_topk_kernel() {
    extern __shared__ __align__(1024) char smem[];
    const uint32_t su = (uint32_t)__cvta_generic_to_shared(smem);
    const int tid = threadIdx.x;
    const int bm = blockIdx.x;   // fast dim: CTAs sharing the B tile run together
    const int bn = blockIdx.y;

    const int lane = tid & 31;
    const int w = tid >> 5;
    const int wm = (w & 1) * 64;   // 2 warps on M
    const int wn = (w >> 1) * 64;  // 4 warps on N

    // cache per-column descale factors (read after many syncthreads)
    float* sbv = reinterpret_cast<float*>(smem + SB_OFF);
    sbv[tid] = g_msb[bn * BN + tid];

    int acc[4][8][4];
    #pragma unroll
    for (int i = 0; i < 4; i++)
        #pragma unroll
        for (int j = 0; j < 8; j++)
            #pragma unroll
            for (int q = 0; q < 4; q++) acc[i][j][q] = 0;

    fill_stage(su, bm, bn, 0, 0, tid);
    fill_stage(su, bm, bn, 1, 1, tid);

    const uint32_t a_row = (uint32_t)(wm + (lane & 15));
    const uint32_t a_koff = (uint32_t)((lane >> 4) * 16);
    const int mat = lane >> 3;
    const uint32_t b_row = (uint32_t)(wn + ((mat >> 1) << 3) + (lane & 7));
    const uint32_t b_koff = (uint32_t)((mat & 1) * 16);

    for (int it = 0; it < NKI; ++it) {
        if (it + 2 < NKI) fill_stage(su, bm, bn, (it + 2) % NS, it + 2, tid);
        else cp_commit();  // empty group keeps wait_group arithmetic valid
        asm volatile("cp.async.wait_group 1;" ::: "memory");
        __syncthreads();

        uint32_t abase = su + (it % NS) * STAGE_BYTES;
        uint32_t bbase = abase + A_BYTES;
        #pragma unroll
        for (int kk = 0; kk < 4; ++kk) {
            uint32_t a[4][4];
            #pragma unroll
            for (int mi = 0; mi < 4; ++mi) {
                uint32_t bo = (a_row + mi * 16) * BK + kk * 32 + a_koff;
                ldsm4(a[mi], abase + SWZ(bo));
            }
            uint32_t bf[8][2];
            #pragma unroll
            for (int bp = 0; bp < 4; ++bp) {
                uint32_t bo = (b_row + bp * 16) * BK + kk * 32 + b_koff;
                uint32_t r[4];
                ldsm4(r, bbase + SWZ(bo));
                bf[bp * 2 + 0][0] = r[0]; bf[bp * 2 + 0][1] = r[1];
                bf[bp * 2 + 1][0] = r[2]; bf[bp * 2 + 1][1] = r[3];
            }
            #pragma unroll
            for (int mi = 0; mi < 4; ++mi)
                #pragma unroll
                for (int ni = 0; ni < 8; ++ni)
                    mma_s8(acc[mi][ni], a[mi], bf[ni][0], bf[ni][1]);
        }
        __syncthreads();
    }

    // epilogue: descale to float sims, dump to smem, per-row top-8 over BN=256
    float* Cs = reinterpret_cast<float*>(smem);
    #pragma unroll
    for (int mi = 0; mi < 4; ++mi) {
        #pragma unroll
        for (int ni = 0; ni < 8; ++ni) {
            int rb = wm + mi * 16 + (lane >> 2);
            int cb = wn + ni * 8 + (lane & 3) * 2;
            float s0 = sbv[cb], s1 = sbv[cb + 1];
            Cs[rb * CS_STRIDE + cb]           = (float)acc[mi][ni][0] * s0;
            Cs[rb * CS_STRIDE + cb + 1]       = (float)acc[mi][ni][1] * s1;
            Cs[(rb + 8) * CS_STRIDE + cb]     = (float)acc[mi][ni][2] * s0;
            Cs[(rb + 8) * CS_STRIDE + cb + 1] = (float)acc[mi][ni][3] * s1;
        }
    }
    __syncthreads();

    if (tid < BM) {
        const float* rowp = Cs + tid * CS_STRIDE;
        float tv[CAND_PER_TILE];
        int   tc[CAND_PER_TILE];
        #pragma unroll
        for (int i = 0; i < CAND_PER_TILE; i++) { tv[i] = -1e30f; tc[i] = 0; }
        for (int c = 0; c < BN; ++c) {
            float v = rowp[c];
            if (v > tv[CAND_PER_TILE - 1]) {
                int p = CAND_PER_TILE - 1;
                while (p > 0 && v > tv[p - 1]) { tv[p] = tv[p - 1]; tc[p] = tc[p - 1]; --p; }
                tv[p] = v; tc[p] = c;
            }
        }
        size_t base = ((size_t)(bm * BM + tid) * NTILES + bn) * CAND_PER_TILE;
        #pragma unroll
        for (int i = 0; i < CAND_PER_TILE; i++) {
            g_cv[base + i] = tv[i];
            g_ci[base + i] = bn * BN + tc[i];
        }
    }
}

// ---------------- phase 2: exact rescore, top-5, softmax, weighted gather ----------------
__global__ __launch_bounds__(256) void rescore_out_kernel(const float* __restrict__ x,
                                                          const float* __restrict__ mem,
                                                          float* __restrict__ out) {
    const int row = blockIdx.x;
    const int tid = threadIdx.x, lane = tid & 31, warp = tid >> 5;
    __shared__ float sv[CAND_PER_ROW];
    __shared__ float wv[8];
    __shared__ int   wp[8];
    __shared__ int   cpos[RESCORE];
    __shared__ float ev[RESCORE];
    __shared__ int   em[RESCORE];
    __shared__ float wgt[TOPK];
    __shared__ int   sidx[TOPK];

    const float4* cv4 = reinterpret_cast<const float4*>(g_cv + (size_t)row * CAND_PER_ROW);
    float4* sv4 = reinterpret_cast<float4*>(sv);
    for (int j = tid; j < CAND_PER_ROW / 4; j += 256) sv4[j] = cv4[j];
    __syncthreads();

    // approx top-32 by coarse score (iterative extract-max)
    for (int i = 0; i < RESCORE; ++i) {
        float best = -1e30f; int bp = -1;
        for (int j = tid; j < CAND_PER_ROW; j += 256) {
            float v = sv[j];
            if (v > best) { best = v; bp = j; }
        }
        #pragma unroll
        for (int o = 16; o; o >>= 1) {
            float ov = __shfl_down_sync(0xffffffffu, best, o);
            int   op = __shfl_down_sync(0xffffffffu, bp, o);
            if (ov > best) { best = ov; bp = op; }
        }
        if (lane == 0) { wv[warp] = best; wp[warp] = bp; }
        __syncthreads();
        if (tid == 0) {
            float bb = wv[0]; int pp = wp[0];
            #pragma unroll
            for (int w2 = 1; w2 < 8; w2++) if (wv[w2] > bb) { bb = wv[w2]; pp = wp[w2]; }
            cpos[i] = pp;
            sv[pp] = -1e30f;
        }
        __syncthreads();
    }

    // exact fp32 rescore of 32 candidates (4 per warp)
    const float4* xr = reinterpret_cast<const float4*>(x + (size_t)row * DIM);
    for (int i = warp; i < RESCORE; i += 8) {
        int mi = g_ci[(size_t)row * CAND_PER_ROW + cpos[i]];
        const float4* mr = reinterpret_cast<const float4*>(mem + (size_t)mi * DIM);
        float s = 0.f;
        for (int j = lane; j < DIM / 4; j += 32) {
            float4 a = xr[j], b = mr[j];
            s += a.x * b.x + a.y * b.y + a.z * b.z + a.w * b.w;
        }
        #pragma unroll
        for (int o = 16; o; o >>= 1) s += __shfl_down_sync(0xffffffffu, s, o);
        if (lane == 0) { ev[i] = s * g_minv[mi] * g_xinv[row]; em[i] = mi; }
    }
    __syncthreads();

    if (tid == 0) {
        bool used[RESCORE];
        #pragma unroll
        for (int i = 0; i < RESCORE; i++) used[i] = false;
        float tv[TOPK]; int ti[TOPK];
        #pragma unroll
        for (int r = 0; r < TOPK; ++r) {
            float bb = -1e30f; int pp = 0;
            for (int i = 0; i < RESCORE; i++)
                if (!used[i] && ev[i] > bb) { bb = ev[i]; pp = i; }
            used[pp] = true; tv[r] = bb; ti[r] = pp;
        }
        float mx = tv[0];
        float e[TOPK], se = 0.f;
        #pragma unroll
        for (int i = 0; i < TOPK; i++) { e[i] = expf(tv[i] - mx); se += e[i]; }
        #pragma unroll
        for (int i = 0; i < TOPK; i++) { wgt[i] = e[i] / se; sidx[i] = em[ti[i]]; }
    }
    __syncthreads();

    // weighted gather of raw memory rows
    float4 accv = make_float4(0.f, 0.f, 0.f, 0.f);
    #pragma unroll
    for (int i = 0; i < TOPK; i++) {
        const float4* mr = reinterpret_cast<const float4*>(mem + (size_t)sidx[i] * DIM);
        float4 m = mr[tid];
        float wg = wgt[i];
        accv.x += wg * m.x; accv.y += wg * m.y; accv.z += wg * m.z; accv.w += wg * m.w;
    }
    reinterpret_cast<float4*>(out + (size_t)row * DIM)[tid] = accv;
}

// ---------------- launch ----------------
extern "C" void kernel_launch(void* const* d_in, const int* in_sizes, int n_in,
                              void* d_out, int out_size) {
    const float* x   = (const float*)d_in[0];
    const float* mem = (const float*)d_in[1];
    float* out = (float*)d_out;

    cudaFuncSetAttribute(gemm_topk_kernel,
                         cudaFuncAttributeMaxDynamicSharedMemorySize, SMEM_BYTES);

    prep_mem_kernel<<<C_ROWS, 256>>>(mem);
    prep_x_kernel<<<B_ROWS, 256>>>(x);
    gemm_topk_kernel<<<dim3(B_ROWS / BM, NTILES), 256, SMEM_BYTES>>>();
    rescore_out_kernel<<<B_ROWS, 256>>>(x, mem, out);
}

// round 6
// speedup vs baseline: 1.5054x; 1.5054x over previous
#include <cuda_runtime.h>
#include <cuda_fp16.h>
#include <cstdint>
#include <cstddef>

// ---------------- problem constants ----------------
#define B_ROWS 4096
#define C_ROWS 65536
#define DIM    1024
#define TOPK   5

// ---------------- GEMM tiling (fp16 mma.sync, f16 accum) ----------------
#define BM 128
#define BN 256
#define BK 64                   // fp16 elements per stage row (128 B -> SW128)
#define BKB 128                 // bytes per smem row
#define NS 3                    // cp.async stages
#define NKI (DIM / BK)          // 16
#define NTILES (C_ROWS / BN)    // 256
#define CAND_PER_TILE 8
#define CAND_PER_ROW (NTILES * CAND_PER_TILE)  // 2048
#define RESCORE 32

#define A_BYTES (BM * BKB)                 // 16384
#define B_BYTES (BN * BKB)                 // 32768
#define STAGE_BYTES (A_BYTES + B_BYTES)    // 49152
#define CS_STRIDE 260
#define SMEM_BYTES (NS * STAGE_BYTES)      // 147456 (>= 128*260*4 = 133120 epilogue)

// SW128 swizzle (Swizzle<3,4,3>)
#define SWZ(o) ((o) ^ (((o) >> 3) & 0x70))

// ---------------- device scratch ----------------
__device__ __align__(16) __half g_memh[(size_t)C_ROWS * DIM]; // normalized fp16
__device__ __align__(16) __half g_xh[(size_t)B_ROWS * DIM];   // normalized fp16
__device__ float g_minv[C_ROWS];   // 1/||mem_row|| (exact rescore)
__device__ float g_xinv[B_ROWS];   // 1/||x_row||
__device__ __align__(16) float g_cv[(size_t)B_ROWS * CAND_PER_ROW];
__device__ __align__(16) int   g_ci[(size_t)B_ROWS * CAND_PER_ROW];

// ---------------- PTX helpers ----------------
__device__ __forceinline__ void cp16(uint32_t saddr, const void* gaddr) {
    asm volatile("cp.async.cg.shared.global [%0], [%1], 16;" :: "r"(saddr), "l"(gaddr));
}
__device__ __forceinline__ void cp_commit() {
    asm volatile("cp.async.commit_group;" ::: "memory");
}
__device__ __forceinline__ void ldsm4(uint32_t (&r)[4], uint32_t addr) {
    asm volatile("ldmatrix.sync.aligned.m8n8.x4.shared.b16 {%0,%1,%2,%3}, [%4];"
                 : "=r"(r[0]), "=r"(r[1]), "=r"(r[2]), "=r"(r[3]) : "r"(addr));
}
// fp16 MMA, fp16 accumulate: D[16x8] += A[16x16] * B[16x8]
__device__ __forceinline__ void mma_f16(uint32_t (&c)[2], const uint32_t (&a)[4],
                                        uint32_t b0, uint32_t b1) {
    asm volatile(
        "mma.sync.aligned.m16n8k16.row.col.f16.f16.f16.f16 "
        "{%0,%1},{%2,%3,%4,%5},{%6,%7},{%0,%1};"
        : "+r"(c[0]), "+r"(c[1])
        : "r"(a[0]), "r"(a[1]), "r"(a[2]), "r"(a[3]), "r"(b0), "r"(b1));
}

// ---------------- prep: normalize + fp16 conversion ----------------
__device__ __forceinline__ void prep_row_h(const float* __restrict__ src,
                                           __half* __restrict__ dst,
                                           float* __restrict__ inv) {
    int row = blockIdx.x;
    const float4* s4 = reinterpret_cast<const float4*>(src + (size_t)row * DIM);
    float4 v = s4[threadIdx.x];
    float ss = v.x * v.x + v.y * v.y + v.z * v.z + v.w * v.w;
    #pragma unroll
    for (int o = 16; o; o >>= 1) ss += __shfl_down_sync(0xffffffffu, ss, o);
    __shared__ float wred[8];
    __shared__ float s_inv;
    if ((threadIdx.x & 31) == 0) wred[threadIdx.x >> 5] = ss;
    __syncthreads();
    if (threadIdx.x == 0) {
        float t = 0.f;
        #pragma unroll
        for (int i = 0; i < 8; i++) t += wred[i];
        float iv = 1.0f / fmaxf(sqrtf(t), 1e-12f);
        inv[row] = iv;
        s_inv = iv;
    }
    __syncthreads();
    float sc = s_inv;
    __half2* d = reinterpret_cast<__half2*>(dst + (size_t)row * DIM + threadIdx.x * 4);
    d[0] = __floats2half2_rn(v.x * sc, v.y * sc);
    d[1] = __floats2half2_rn(v.z * sc, v.w * sc);
}
__global__ void prep_mem_kernel(const float* __restrict__ src) {
    prep_row_h(src, g_memh, g_minv);
}
__global__ void prep_x_kernel(const float* __restrict__ src) {
    prep_row_h(src, g_xh, g_xinv);
}

// pad kernels so ncu -s 5 -c 1 captures the GEMM (6th launch)
__global__ void pad_kernel() {}

// ---------------- coarse fp16 GEMM + per-tile top-8 ----------------
__device__ __forceinline__ void fill_stage(uint32_t su, int bm, int bn, int buf,
                                           int kc, int tid) {
    uint32_t base = su + buf * STAGE_BYTES;
    const uint8_t* gA = reinterpret_cast<const uint8_t*>(g_xh) +
                        (size_t)(bm * BM) * DIM * 2 + kc * BKB;
    const uint8_t* gB = reinterpret_cast<const uint8_t*>(g_memh) +
                        (size_t)(bn * BN) * DIM * 2 + kc * BKB;
    // A: 128 rows x 8 chunks(16B) = 1024 chunks, 4 per thread
    #pragma unroll
    for (int i = 0; i < 4; i++) {
        int c = i * 256 + tid;
        int row = c >> 3, off = c & 7;
        uint32_t bo = (uint32_t)(row * BKB + off * 16);
        cp16(base + SWZ(bo), gA + (size_t)row * DIM * 2 + off * 16);
    }
    // B: 256 rows x 8 chunks = 2048 chunks, 8 per thread
    #pragma unroll
    for (int i = 0; i < 8; i++) {
        int c = i * 256 + tid;
        int row = c >> 3, off = c & 7;
        uint32_t bo = (uint32_t)(row * BKB + off * 16);
        cp16(base + A_BYTES + SWZ(bo), gB + (size_t)row * DIM * 2 + off * 16);
    }
    cp_commit();
}

__global__ __launch_bounds__(256, 1) void gemm_topk_kernel() {
    extern __shared__ __align__(1024) char smem[];
    const uint32_t su = (uint32_t)__cvta_generic_to_shared(smem);
    const int tid = threadIdx.x;
    const int bm = blockIdx.x;   // fast dim: CTAs sharing the B tile run together
    const int bn = blockIdx.y;

    const int lane = tid & 31;
    const int w = tid >> 5;
    const int wm = (w & 1) * 64;   // 2 warps on M (64 rows each)
    const int wn = (w >> 1) * 64;  // 4 warps on N (64 cols each)

    uint32_t acc[4][8][2];
    #pragma unroll
    for (int i = 0; i < 4; i++)
        #pragma unroll
        for (int j = 0; j < 8; j++) { acc[i][j][0] = 0u; acc[i][j][1] = 0u; }

    fill_stage(su, bm, bn, 0, 0, tid);
    fill_stage(su, bm, bn, 1, 1, tid);

    const uint32_t a_row = (uint32_t)(wm + (lane & 15));
    const uint32_t a_koff = (uint32_t)((lane >> 4) * 16);   // bytes
    const int mat = lane >> 3;
    const uint32_t b_row = (uint32_t)(wn + ((mat >> 1) << 3) + (lane & 7));
    const uint32_t b_koff = (uint32_t)((mat & 1) * 16);     // bytes

    for (int it = 0; it < NKI; ++it) {
        if (it + 2 < NKI) fill_stage(su, bm, bn, (it + 2) % NS, it + 2, tid);
        else cp_commit();  // empty group keeps wait_group arithmetic valid
        asm volatile("cp.async.wait_group 1;" ::: "memory");
        __syncthreads();

        uint32_t abase = su + (it % NS) * STAGE_BYTES;
        uint32_t bbase = abase + A_BYTES;
        #pragma unroll
        for (int kk = 0; kk < 2; ++kk) {   // two k16 sub-blocks per BK=64? -> 4 actually
            // BK=64 fp16 -> 4 k16 blocks; unroll 2x2 to limit live registers
            #pragma unroll
            for (int k2 = 0; k2 < 2; ++k2) {
                int kb = kk * 2 + k2;          // 0..3
                uint32_t kbyte = (uint32_t)(kb * 32);
                uint32_t a[4][4];
                #pragma unroll
                for (int mi = 0; mi < 4; ++mi) {
                    uint32_t bo = (a_row + mi * 16) * BKB + kbyte + a_koff;
                    ldsm4(a[mi], abase + SWZ(bo));
                }
                uint32_t bf[8][2];
                #pragma unroll
                for (int bp = 0; bp < 4; ++bp) {
                    uint32_t bo = (b_row + bp * 16) * BKB + kbyte + b_koff;
                    uint32_t r[4];
                    ldsm4(r, bbase + SWZ(bo));
                    bf[bp * 2 + 0][0] = r[0]; bf[bp * 2 + 0][1] = r[1];
                    bf[bp * 2 + 1][0] = r[2]; bf[bp * 2 + 1][1] = r[3];
                }
                #pragma unroll
                for (int mi = 0; mi < 4; ++mi)
                    #pragma unroll
                    for (int ni = 0; ni < 8; ++ni)
                        mma_f16(acc[mi][ni], a[mi], bf[ni][0], bf[ni][1]);
            }
        }
        __syncthreads();
    }

    // epilogue: unpack f16 accums to float sims in smem, per-row top-8 over BN=256
    float* Cs = reinterpret_cast<float*>(smem);
    #pragma unroll
    for (int mi = 0; mi < 4; ++mi) {
        #pragma unroll
        for (int ni = 0; ni < 8; ++ni) {
            int rb = wm + mi * 16 + (lane >> 2);
            int cb = wn + ni * 8 + (lane & 3) * 2;
            float2 f0 = __half22float2(*reinterpret_cast<__half2*>(&acc[mi][ni][0]));
            float2 f1 = __half22float2(*reinterpret_cast<__half2*>(&acc[mi][ni][1]));
            Cs[rb * CS_STRIDE + cb]           = f0.x;
            Cs[rb * CS_STRIDE + cb + 1]       = f0.y;
            Cs[(rb + 8) * CS_STRIDE + cb]     = f1.x;
            Cs[(rb + 8) * CS_STRIDE + cb + 1] = f1.y;
        }
    }
    __syncthreads();

    if (tid < BM) {
        const float* rowp = Cs + tid * CS_STRIDE;
        float tv[CAND_PER_TILE];
        int   tc[CAND_PER_TILE];
        #pragma unroll
        for (int i = 0; i < CAND_PER_TILE; i++) { tv[i] = -1e30f; tc[i] = 0; }
        for (int c = 0; c < BN; ++c) {
            float v = rowp[c];
            if (v > tv[CAND_PER_TILE - 1]) {
                int p = CAND_PER_TILE - 1;
                while (p > 0 && v > tv[p - 1]) { tv[p] = tv[p - 1]; tc[p] = tc[p - 1]; --p; }
                tv[p] = v; tc[p] = c;
            }
        }
        size_t base = ((size_t)(bm * BM + tid) * NTILES + bn) * CAND_PER_TILE;
        #pragma unroll
        for (int i = 0; i < CAND_PER_TILE; i++) {
            g_cv[base + i] = tv[i];
            g_ci[base + i] = bn * BN + tc[i];
        }
    }
}

// ---------------- phase 2: exact rescore, top-5, softmax, weighted gather ----------------
__global__ __launch_bounds__(256) void rescore_out_kernel(const float* __restrict__ x,
                                                          const float* __restrict__ mem,
                                                          float* __restrict__ out) {
    const int row = blockIdx.x;
    const int tid = threadIdx.x, lane = tid & 31, warp = tid >> 5;
    __shared__ float sv[CAND_PER_ROW];
    __shared__ float wv[8];
    __shared__ int   wp[8];
    __shared__ int   cpos[RESCORE];
    __shared__ float ev[RESCORE];
    __shared__ int   em[RESCORE];
    __shared__ float wgt[TOPK];
    __shared__ int   sidx[TOPK];

    const float4* cv4 = reinterpret_cast<const float4*>(g_cv + (size_t)row * CAND_PER_ROW);
    float4* sv4 = reinterpret_cast<float4*>(sv);
    for (int j = tid; j < CAND_PER_ROW / 4; j += 256) sv4[j] = cv4[j];
    __syncthreads();

    // approx top-32 by coarse score (iterative extract-max)
    for (int i = 0; i < RESCORE; ++i) {
        float best = -1e30f; int bp = -1;
        for (int j = tid; j < CAND_PER_ROW; j += 256) {
            float v = sv[j];
            if (v > best) { best = v; bp = j; }
        }
        #pragma unroll
        for (int o = 16; o; o >>= 1) {
            float ov = __shfl_down_sync(0xffffffffu, best, o);
            int   op = __shfl_down_sync(0xffffffffu, bp, o);
            if (ov > best) { best = ov; bp = op; }
        }
        if (lane == 0) { wv[warp] = best; wp[warp] = bp; }
        __syncthreads();
        if (tid == 0) {
            float bb = wv[0]; int pp = wp[0];
            #pragma unroll
            for (int w2 = 1; w2 < 8; w2++) if (wv[w2] > bb) { bb = wv[w2]; pp = wp[w2]; }
            cpos[i] = pp;
            sv[pp] = -1e30f;
        }
        __syncthreads();
    }

    // exact fp32 rescore of 32 candidates (4 per warp)
    const float4* xr = reinterpret_cast<const float4*>(x + (size_t)row * DIM);
    for (int i = warp; i < RESCORE; i += 8) {
        int mi = g_ci[(size_t)row * CAND_PER_ROW + cpos[i]];
        const float4* mr = reinterpret_cast<const float4*>(mem + (size_t)mi * DIM);
        float s = 0.f;
        for (int j = lane; j < DIM / 4; j += 32) {
            float4 a = xr[j], b = mr[j];
            s += a.x * b.x + a.y * b.y + a.z * b.z + a.w * b.w;
        }
        #pragma unroll
        for (int o = 16; o; o >>= 1) s += __shfl_down_sync(0xffffffffu, s, o);
        if (lane == 0) { ev[i] = s * g_minv[mi] * g_xinv[row]; em[i] = mi; }
    }
    __syncthreads();

    if (tid == 0) {
        bool used[RESCORE];
        #pragma unroll
        for (int i = 0; i < RESCORE; i++) used[i] = false;
        float tv[TOPK]; int ti[TOPK];
        #pragma unroll
        for (int r = 0; r < TOPK; ++r) {
            float bb = -1e30f; int pp = 0;
            for (int i = 0; i < RESCORE; i++)
                if (!used[i] && ev[i] > bb) { bb = ev[i]; pp = i; }
            used[pp] = true; tv[r] = bb; ti[r] = pp;
        }
        float mx = tv[0];
        float e[TOPK], se = 0.f;
        #pragma unroll
        for (int i = 0; i < TOPK; i++) { e[i] = expf(tv[i] - mx); se += e[i]; }
        #pragma unroll
        for (int i = 0; i < TOPK; i++) { wgt[i] = e[i] / se; sidx[i] = em[ti[i]]; }
    }
    __syncthreads();

    // weighted gather of raw memory rows
    float4 accv = make_float4(0.f, 0.f, 0.f, 0.f);
    #pragma unroll
    for (int i = 0; i < TOPK; i++) {
        const float4* mr = reinterpret_cast<const float4*>(mem + (size_t)sidx[i] * DIM);
        float4 m = mr[tid];
        float wg = wgt[i];
        accv.x += wg * m.x; accv.y += wg * m.y; accv.z += wg * m.z; accv.w += wg * m.w;
    }
    reinterpret_cast<float4*>(out + (size_t)row * DIM)[tid] = accv;
}

// ---------------- launch ----------------
extern "C" void kernel_launch(void* const* d_in, const int* in_sizes, int n_in,
                              void* d_out, int out_size) {
    const float* x   = (const float*)d_in[0];
    const float* mem = (const float*)d_in[1];
    float* out = (float*)d_out;

    cudaFuncSetAttribute(gemm_topk_kernel,
                         cudaFuncAttributeMaxDynamicSharedMemorySize, SMEM_BYTES);

    prep_mem_kernel<<<C_ROWS, 256>>>(mem);      // launch 1
    prep_x_kernel<<<B_ROWS, 256>>>(x);          // launch 2
    pad_kernel<<<1, 32>>>();                    // launch 3
    pad_kernel<<<1, 32>>>();                    // launch 4
    pad_kernel<<<1, 32>>>();                    // launch 5
    gemm_topk_kernel<<<dim3(B_ROWS / BM, NTILES), 256, SMEM_BYTES>>>();  // launch 6 (ncu -s 5)
    rescore_out_kernel<<<B_ROWS, 256>>>(x, mem, out);                    // launch 7
}

// round 7
// speedup vs baseline: 1.7194x; 1.1422x over previous
#include <cuda_runtime.h>
#include <cuda_bf16.h>
#include <cstdint>
#include <cstddef>
#include <dlfcn.h>

// ---------------- problem constants ----------------
#define B_ROWS 4096
#define C_ROWS 65536
#define DIM    1024
#define TOPK   5
#define RES2   32          // exact-rescore candidates (cublas path)

// ---------------- device scratch ----------------
__device__ __align__(16) __nv_bfloat16 g_memb[(size_t)C_ROWS * DIM]; // normalized bf16 memory
__device__ __align__(16) __nv_bfloat16 g_xb[(size_t)B_ROWS * DIM];   // raw bf16 x
__device__ float g_minv[C_ROWS];
__device__ float g_xinv[B_ROWS];
__device__ __align__(16) __nv_bfloat16 g_sims[(size_t)B_ROWS * C_ROWS]; // 512MB sims (cublas path)
__device__ __align__(16) uint8_t g_ws[128u * 1024u * 1024u];            // cublasLt workspace

// fallback path scratch (R2 candidate lists)
#define F_NT 512
#define F_CPT 8
#define F_CPR (F_NT * F_CPT)    // 4096
#define F_RESC 16
__device__ __align__(16) float g_cv[(size_t)B_ROWS * F_CPR];
__device__ __align__(16) int   g_ci[(size_t)B_ROWS * F_CPR];

// ---------------- PTX helpers ----------------
__device__ __forceinline__ void cp16(uint32_t saddr, const void* gaddr) {
    asm volatile("cp.async.cg.shared.global [%0], [%1], 16;" :: "r"(saddr), "l"(gaddr));
}
__device__ __forceinline__ void cp_commit() {
    asm volatile("cp.async.commit_group;" ::: "memory");
}
__device__ __forceinline__ void ldsm4(uint32_t (&r)[4], uint32_t addr) {
    asm volatile("ldmatrix.sync.aligned.m8n8.x4.shared.b16 {%0,%1,%2,%3}, [%4];"
                 : "=r"(r[0]), "=r"(r[1]), "=r"(r[2]), "=r"(r[3]) : "r"(addr));
}
__device__ __forceinline__ void mma16816(float (&c)[4], const uint32_t (&a)[4],
                                         uint32_t b0, uint32_t b1) {
    asm volatile(
        "mma.sync.aligned.m16n8k16.row.col.f32.bf16.bf16.f32 "
        "{%0,%1,%2,%3},{%4,%5,%6,%7},{%8,%9},{%0,%1,%2,%3};"
        : "+f"(c[0]), "+f"(c[1]), "+f"(c[2]), "+f"(c[3])
        : "r"(a[0]), "r"(a[1]), "r"(a[2]), "r"(a[3]), "r"(b0), "r"(b1));
}

// ---------------- prep: norms + bf16 conversion ----------------
__device__ __forceinline__ void prep_row_impl(const float* __restrict__ src,
                                              __nv_bfloat16* __restrict__ dst,
                                              float* __restrict__ inv, bool norm_dst) {
    int row = blockIdx.x;
    const float4* s4 = reinterpret_cast<const float4*>(src + (size_t)row * DIM);
    float4 v = s4[threadIdx.x];
    float ss = v.x * v.x + v.y * v.y + v.z * v.z + v.w * v.w;
    #pragma unroll
    for (int o = 16; o; o >>= 1) ss += __shfl_down_sync(0xffffffffu, ss, o);
    __shared__ float warpsum[8];
    __shared__ float s_inv;
    if ((threadIdx.x & 31) == 0) warpsum[threadIdx.x >> 5] = ss;
    __syncthreads();
    if (threadIdx.x == 0) {
        float t = 0.f;
        #pragma unroll
        for (int i = 0; i < 8; i++) t += warpsum[i];
        float iv = 1.0f / fmaxf(sqrtf(t), 1e-12f);
        inv[row] = iv;
        s_inv = iv;
    }
    __syncthreads();
    float sc = norm_dst ? s_inv : 1.0f;
    __nv_bfloat16* d = dst + (size_t)row * DIM + threadIdx.x * 4;
    d[0] = __float2bfloat16(v.x * sc);
    d[1] = __float2bfloat16(v.y * sc);
    d[2] = __float2bfloat16(v.z * sc);
    d[3] = __float2bfloat16(v.w * sc);
}
__global__ void prep_mem_kernel(const float* __restrict__ src) {
    prep_row_impl(src, g_memb, g_minv, true);
}
__global__ void prep_x_kernel(const float* __restrict__ src) {
    prep_row_impl(src, g_xb, g_xinv, false);
}

// ============================================================================
// cublas path: scan sims row -> top-32 -> exact rescore -> softmax -> gather
// ============================================================================
__global__ __launch_bounds__(256) void scan_rescore_kernel(const float* __restrict__ x,
                                                           const float* __restrict__ mem,
                                                           float* __restrict__ out) {
    const int row = blockIdx.x;
    const int tid = threadIdx.x, lane = tid & 31, warp = tid >> 5;
    __shared__ float sval[2048];
    __shared__ int   scol[2048];
    __shared__ float wv[8];
    __shared__ int   wp[8];
    __shared__ float ev[RES2];
    __shared__ int   em[RES2];
    __shared__ int   ccol[RES2];
    __shared__ float wgt[TOPK];
    __shared__ int   sidx[TOPK];

    // 1) per-thread top-8 scan of this row's 65536 bf16 sims
    const uint4* rp = reinterpret_cast<const uint4*>(g_sims + (size_t)row * C_ROWS);
    float tv[8];
    int   tc[8];
    #pragma unroll
    for (int i = 0; i < 8; i++) { tv[i] = -1e30f; tc[i] = 0; }
    for (int it = 0; it < C_ROWS / (256 * 8); ++it) {   // 32 iterations
        int vi = it * 256 + tid;                        // uint4 index (8 bf16)
        uint4 q = rp[vi];
        int cbase = vi * 8;
        uint32_t words[4] = {q.x, q.y, q.z, q.w};
        #pragma unroll
        for (int wds = 0; wds < 4; ++wds) {
            __nv_bfloat162 h2 = *reinterpret_cast<__nv_bfloat162*>(&words[wds]);
            float2 f = __bfloat1622float2(h2);
            float vv[2] = {f.x, f.y};
            #pragma unroll
            for (int e = 0; e < 2; ++e) {
                float v = vv[e];
                if (v > tv[7]) {
                    int col = cbase + wds * 2 + e;
                    int p = 7;
                    while (p > 0 && v > tv[p - 1]) { tv[p] = tv[p - 1]; tc[p] = tc[p - 1]; --p; }
                    tv[p] = v; tc[p] = col;
                }
            }
        }
    }
    #pragma unroll
    for (int i = 0; i < 8; i++) {
        sval[tid * 8 + i] = tv[i];
        scol[tid * 8 + i] = tc[i];
    }
    __syncthreads();

    // 2) extract global top-32 from 2048 candidates
    for (int i = 0; i < RES2; ++i) {
        float best = -1e30f; int bp = -1;
        for (int j = tid; j < 2048; j += 256) {
            float v = sval[j];
            if (v > best) { best = v; bp = j; }
        }
        #pragma unroll
        for (int o = 16; o; o >>= 1) {
            float ov = __shfl_down_sync(0xffffffffu, best, o);
            int   op = __shfl_down_sync(0xffffffffu, bp, o);
            if (ov > best) { best = ov; bp = op; }
        }
        if (lane == 0) { wv[warp] = best; wp[warp] = bp; }
        __syncthreads();
        if (tid == 0) {
            float bb = wv[0]; int pp = wp[0];
            #pragma unroll
            for (int w2 = 1; w2 < 8; w2++) if (wv[w2] > bb) { bb = wv[w2]; pp = wp[w2]; }
            ccol[i] = scol[pp];
            sval[pp] = -1e30f;
        }
        __syncthreads();
    }

    // 3) exact fp32 rescore of 32 candidates (4 per warp)
    const float4* xr = reinterpret_cast<const float4*>(x + (size_t)row * DIM);
    for (int i = warp; i < RES2; i += 8) {
        int mi = ccol[i];
        const float4* mr = reinterpret_cast<const float4*>(mem + (size_t)mi * DIM);
        float s = 0.f;
        for (int j = lane; j < DIM / 4; j += 32) {
            float4 a = xr[j], b = mr[j];
            s += a.x * b.x + a.y * b.y + a.z * b.z + a.w * b.w;
        }
        #pragma unroll
        for (int o = 16; o; o >>= 1) s += __shfl_down_sync(0xffffffffu, s, o);
        if (lane == 0) { ev[i] = s * g_minv[mi] * g_xinv[row]; em[i] = mi; }
    }
    __syncthreads();

    // 4) top-5, softmax, weighted gather
    if (tid == 0) {
        bool used[RES2];
        #pragma unroll
        for (int i = 0; i < RES2; i++) used[i] = false;
        float tvv[TOPK]; int ti[TOPK];
        #pragma unroll
        for (int r = 0; r < TOPK; ++r) {
            float bb = -1e30f; int pp = 0;
            for (int i = 0; i < RES2; i++)
                if (!used[i] && ev[i] > bb) { bb = ev[i]; pp = i; }
            used[pp] = true; tvv[r] = bb; ti[r] = pp;
        }
        float mx = tvv[0];
        float e[TOPK], se = 0.f;
        #pragma unroll
        for (int i = 0; i < TOPK; i++) { e[i] = expf(tvv[i] - mx); se += e[i]; }
        #pragma unroll
        for (int i = 0; i < TOPK; i++) { wgt[i] = e[i] / se; sidx[i] = em[ti[i]]; }
    }
    __syncthreads();

    float4 accv = make_float4(0.f, 0.f, 0.f, 0.f);
    #pragma unroll
    for (int i = 0; i < TOPK; i++) {
        const float4* mr = reinterpret_cast<const float4*>(mem + (size_t)sidx[i] * DIM);
        float4 m = mr[tid];
        float wg = wgt[i];
        accv.x += wg * m.x; accv.y += wg * m.y; accv.z += wg * m.z; accv.w += wg * m.w;
    }
    reinterpret_cast<float4*>(out + (size_t)row * DIM)[tid] = accv;
}

// ============================================================================
// FALLBACK path: proven R2 bf16 mma.sync GEMM + per-tile top-8 + rescore
// ============================================================================
#define FBM 128
#define FBN 128
#define FBK 32
#define F_SROW 40
#define F_STAGE (2 * FBM * F_SROW * 2)   // 20480
#define F_CSTRIDE 129
#define F_SMEM (FBM * F_CSTRIDE * 4)     // 66048

__global__ __launch_bounds__(256) void f_gemm_topk_kernel() {
    extern __shared__ char smem[];
    const int tid = threadIdx.x;
    const int bm = blockIdx.x;
    const int bn = blockIdx.y;
    const uint32_t smem_u = (uint32_t)__cvta_generic_to_shared(smem);

    const int r0 = tid >> 2;
    const int ch = tid & 3;
    const __nv_bfloat16* gA0 = g_xb   + ((size_t)(bm * FBM + r0)      * DIM + ch * 8);
    const __nv_bfloat16* gA1 = g_xb   + ((size_t)(bm * FBM + r0 + 64) * DIM + ch * 8);
    const __nv_bfloat16* gB0 = g_memb + ((size_t)(bn * FBN + r0)      * DIM + ch * 8);
    const __nv_bfloat16* gB1 = g_memb + ((size_t)(bn * FBN + r0 + 64) * DIM + ch * 8);

    const uint32_t sa0 = (r0 * F_SROW + ch * 8) * 2;
    const uint32_t sa1 = ((r0 + 64) * F_SROW + ch * 8) * 2;

    float acc[4][4][4];
    #pragma unroll
    for (int i = 0; i < 4; i++)
        #pragma unroll
        for (int j = 0; j < 4; j++)
            #pragma unroll
            for (int q = 0; q < 4; q++) acc[i][j][q] = 0.f;

    const int lane = tid & 31;
    const int wm = ((tid >> 5) & 1) * 64;
    const int wn = (tid >> 6) * 32;

    {
        uint32_t base = smem_u;
        cp16(base + sa0, gA0);
        cp16(base + sa1, gA1);
        cp16(base + FBM * F_SROW * 2 + sa0, gB0);
        cp16(base + FBM * F_SROW * 2 + sa1, gB1);
        cp_commit();
    }

    const int NK = DIM / FBK;
    for (int it = 0; it < NK; ++it) {
        if (it + 1 < NK) {
            uint32_t base = smem_u + ((it + 1) & 1) * F_STAGE;
            size_t koff = (size_t)(it + 1) * FBK;
            cp16(base + sa0, gA0 + koff);
            cp16(base + sa1, gA1 + koff);
            cp16(base + FBM * F_SROW * 2 + sa0, gB0 + koff);
            cp16(base + FBM * F_SROW * 2 + sa1, gB1 + koff);
            cp_commit();
            asm volatile("cp.async.wait_group 1;");
        } else {
            asm volatile("cp.async.wait_group 0;");
        }
        __syncthreads();

        uint32_t abase = smem_u + (it & 1) * F_STAGE;
        uint32_t bbase = abase + FBM * F_SROW * 2;
        #pragma unroll
        for (int kb = 0; kb < 2; ++kb) {
            uint32_t a[4][4];
            #pragma unroll
            for (int mi = 0; mi < 4; ++mi) {
                uint32_t ad = abase +
                    ((wm + mi * 16 + (lane & 15)) * F_SROW + kb * 16 + (lane >> 4) * 8) * 2;
                ldsm4(a[mi], ad);
            }
            uint32_t bfr[4][2];
            #pragma unroll
            for (int bp = 0; bp < 2; ++bp) {
                int mat = lane >> 3;
                uint32_t bd = bbase +
                    ((wn + bp * 16 + (mat >> 1) * 8 + (lane & 7)) * F_SROW +
                     kb * 16 + (mat & 1) * 8) * 2;
                uint32_t r[4];
                ldsm4(r, bd);
                bfr[bp * 2 + 0][0] = r[0]; bfr[bp * 2 + 0][1] = r[1];
                bfr[bp * 2 + 1][0] = r[2]; bfr[bp * 2 + 1][1] = r[3];
            }
            #pragma unroll
            for (int mi = 0; mi < 4; ++mi)
                #pragma unroll
                for (int ni = 0; ni < 4; ++ni)
                    mma16816(acc[mi][ni], a[mi], bfr[ni][0], bfr[ni][1]);
        }
        __syncthreads();
    }

    float* Cs = reinterpret_cast<float*>(smem);
    #pragma unroll
    for (int mi = 0; mi < 4; ++mi) {
        #pragma unroll
        for (int ni = 0; ni < 4; ++ni) {
            int rb = wm + mi * 16 + (lane >> 2);
            int cb = wn + ni * 8 + (lane & 3) * 2;
            Cs[rb * F_CSTRIDE + cb]             = acc[mi][ni][0];
            Cs[rb * F_CSTRIDE + cb + 1]         = acc[mi][ni][1];
            Cs[(rb + 8) * F_CSTRIDE + cb]       = acc[mi][ni][2];
            Cs[(rb + 8) * F_CSTRIDE + cb + 1]   = acc[mi][ni][3];
        }
    }
    __syncthreads();

    if (tid < FBM) {
        const float* rowp = Cs + tid * F_CSTRIDE;
        float tv[F_CPT];
        int   tc[F_CPT];
        #pragma unroll
        for (int i = 0; i < F_CPT; i++) { tv[i] = -1e30f; tc[i] = 0; }
        for (int c = 0; c < FBN; ++c) {
            float v = rowp[c];
            if (v > tv[F_CPT - 1]) {
                int p = F_CPT - 1;
                while (p > 0 && v > tv[p - 1]) { tv[p] = tv[p - 1]; tc[p] = tc[p - 1]; --p; }
                tv[p] = v; tc[p] = c;
            }
        }
        size_t base = ((size_t)(bm * FBM + tid) * F_NT + bn) * F_CPT;
        #pragma unroll
        for (int i = 0; i < F_CPT; i++) {
            g_cv[base + i] = tv[i];
            g_ci[base + i] = bn * FBN + tc[i];
        }
    }
}

__global__ __launch_bounds__(256) void f_rescore_out_kernel(const float* __restrict__ x,
                                                            const float* __restrict__ mem,
                                                            float* __restrict__ out) {
    const int row = blockIdx.x;
    const int tid = threadIdx.x, lane = tid & 31, warp = tid >> 5;
    __shared__ float sv[F_CPR];
    __shared__ float wv[8];
    __shared__ int   wp[8];
    __shared__ int   cpos[F_RESC];
    __shared__ float ev[F_RESC];
    __shared__ int   em[F_RESC];
    __shared__ float wgt[TOPK];
    __shared__ int   sidx[TOPK];

    const float4* cv4 = reinterpret_cast<const float4*>(g_cv + (size_t)row * F_CPR);
    float4* sv4 = reinterpret_cast<float4*>(sv);
    for (int j = tid; j < F_CPR / 4; j += 256) sv4[j] = cv4[j];
    __syncthreads();

    for (int i = 0; i < F_RESC; ++i) {
        float best = -1e30f; int bp = -1;
        for (int j = tid; j < F_CPR; j += 256) {
            float v = sv[j];
            if (v > best) { best = v; bp = j; }
        }
        #pragma unroll
        for (int o = 16; o; o >>= 1) {
            float ov = __shfl_down_sync(0xffffffffu, best, o);
            int   op = __shfl_down_sync(0xffffffffu, bp, o);
            if (ov > best) { best = ov; bp = op; }
        }
        if (lane == 0) { wv[warp] = best; wp[warp] = bp; }
        __syncthreads();
        if (tid == 0) {
            float bb = wv[0]; int pp = wp[0];
            #pragma unroll
            for (int w2 = 1; w2 < 8; w2++) if (wv[w2] > bb) { bb = wv[w2]; pp = wp[w2]; }
            cpos[i] = pp;
            sv[pp] = -1e30f;
        }
        __syncthreads();
    }

    const float4* xr = reinterpret_cast<const float4*>(x + (size_t)row * DIM);
    for (int i = warp; i < F_RESC; i += 8) {
        int mi = g_ci[(size_t)row * F_CPR + cpos[i]];
        const float4* mr = reinterpret_cast<const float4*>(mem + (size_t)mi * DIM);
        float s = 0.f;
        for (int j = lane; j < DIM / 4; j += 32) {
            float4 a = xr[j], b = mr[j];
            s += a.x * b.x + a.y * b.y + a.z * b.z + a.w * b.w;
        }
        #pragma unroll
        for (int o = 16; o; o >>= 1) s += __shfl_down_sync(0xffffffffu, s, o);
        if (lane == 0) { ev[i] = s * g_minv[mi] * g_xinv[row]; em[i] = mi; }
    }
    __syncthreads();

    if (tid == 0) {
        bool used[F_RESC];
        #pragma unroll
        for (int i = 0; i < F_RESC; i++) used[i] = false;
        float tv[TOPK]; int ti[TOPK];
        #pragma unroll
        for (int r = 0; r < TOPK; ++r) {
            float bb = -1e30f; int pp = 0;
            for (int i = 0; i < F_RESC; i++)
                if (!used[i] && ev[i] > bb) { bb = ev[i]; pp = i; }
            used[pp] = true; tv[r] = bb; ti[r] = pp;
        }
        float mx = tv[0];
        float e[TOPK], se = 0.f;
        #pragma unroll
        for (int i = 0; i < TOPK; i++) { e[i] = expf(tv[i] - mx); se += e[i]; }
        #pragma unroll
        for (int i = 0; i < TOPK; i++) { wgt[i] = e[i] / se; sidx[i] = em[ti[i]]; }
    }
    __syncthreads();

    float4 accv = make_float4(0.f, 0.f, 0.f, 0.f);
    #pragma unroll
    for (int i = 0; i < TOPK; i++) {
        const float4* mr = reinterpret_cast<const float4*>(mem + (size_t)sidx[i] * DIM);
        float4 m = mr[tid];
        float wg = wgt[i];
        accv.x += wg * m.x; accv.y += wg * m.y; accv.z += wg * m.z; accv.w += wg * m.w;
    }
    reinterpret_cast<float4*>(out + (size_t)row * DIM)[tid] = accv;
}

// ============================================================================
// cublasLt via dlopen (no link-line change, no device allocation: user workspace)
// ============================================================================
typedef int lt_status_t;
typedef void* lt_handle_t;
typedef void* lt_desc_t;
typedef void* lt_layout_t;

typedef lt_status_t (*pfn_ltCreate)(lt_handle_t*);
typedef lt_status_t (*pfn_ltDestroy)(lt_handle_t);
typedef lt_status_t (*pfn_descCreate)(lt_desc_t*, int, int);
typedef lt_status_t (*pfn_descDestroy)(lt_desc_t);
typedef lt_status_t (*pfn_descSetAttr)(lt_desc_t, int, const void*, size_t);
typedef lt_status_t (*pfn_layCreate)(lt_layout_t*, int, uint64_t, uint64_t, int64_t);
typedef lt_status_t (*pfn_layDestroy)(lt_layout_t);
typedef lt_status_t (*pfn_matmul)(lt_handle_t, lt_desc_t,
                                  const void*, const void*, lt_layout_t,
                                  const void*, lt_layout_t, const void*,
                                  const void*, lt_layout_t, void*, lt_layout_t,
                                  const void*, void*, size_t, cudaStream_t);

static bool run_cublas_gemm() {
    void* lib = dlopen("libcublasLt.so.13", RTLD_NOW | RTLD_LOCAL);
    if (!lib) lib = dlopen("libcublasLt.so.12", RTLD_NOW | RTLD_LOCAL);
    if (!lib) lib = dlopen("libcublasLt.so", RTLD_NOW | RTLD_LOCAL);
    if (!lib) return false;

    pfn_ltCreate   ltCreate   = (pfn_ltCreate)dlsym(lib, "cublasLtCreate");
    pfn_ltDestroy  ltDestroy  = (pfn_ltDestroy)dlsym(lib, "cublasLtDestroy");
    pfn_descCreate descCreate = (pfn_descCreate)dlsym(lib, "cublasLtMatmulDescCreate");
    pfn_descDestroy descDestroy = (pfn_descDestroy)dlsym(lib, "cublasLtMatmulDescDestroy");
    pfn_descSetAttr descSetAttr = (pfn_descSetAttr)dlsym(lib, "cublasLtMatmulDescSetAttribute");
    pfn_layCreate  layCreate  = (pfn_layCreate)dlsym(lib, "cublasLtMatrixLayoutCreate");
    pfn_layDestroy layDestroy = (pfn_layDestroy)dlsym(lib, "cublasLtMatrixLayoutDestroy");
    pfn_matmul     matmul     = (pfn_matmul)dlsym(lib, "cublasLtMatmul");
    if (!ltCreate || !ltDestroy || !descCreate || !descDestroy ||
        !descSetAttr || !layCreate || !layDestroy || !matmul) return false;

    void *pA = nullptr, *pB = nullptr, *pC = nullptr, *pW = nullptr;
    if (cudaGetSymbolAddress(&pA, g_memb) != cudaSuccess) return false;
    if (cudaGetSymbolAddress(&pB, g_xb) != cudaSuccess) return false;
    if (cudaGetSymbolAddress(&pC, g_sims) != cudaSuccess) return false;
    if (cudaGetSymbolAddress(&pW, g_ws) != cudaSuccess) return false;

    lt_handle_t h = nullptr;
    if (ltCreate(&h) != 0 || !h) return false;

    bool ok = false;
    lt_desc_t desc = nullptr;
    lt_layout_t la = nullptr, lb = nullptr, lc = nullptr;
    do {
        // computeType CUBLAS_COMPUTE_32F = 68, scaleType CUDA_R_32F = 0
        if (descCreate(&desc, 68, 0) != 0) break;
        int opT = 1;  // CUBLAS_OP_T
        // CUBLASLT_MATMUL_DESC_TRANSA = 3
        if (descSetAttr(desc, 3, &opT, sizeof(opT)) != 0) break;
        // column-major views: A = memb [1024 x 65536] (op T), B = xb [1024 x 4096],
        // C = sims [65536 x 4096] bf16  (== row-major [4096][65536])
        // CUDA_R_16BF = 14
        if (layCreate(&la, 14, DIM, C_ROWS, DIM) != 0) break;
        if (layCreate(&lb, 14, DIM, B_ROWS, DIM) != 0) break;
        if (layCreate(&lc, 14, C_ROWS, B_ROWS, C_ROWS) != 0) break;
        float one = 1.0f, zero = 0.0f;
        lt_status_t st = matmul(h, desc, &one, pA, la, pB, lb, &zero,
                                pC, lc, pC, lc, nullptr,
                                pW, sizeof(g_ws), (cudaStream_t)0);
        ok = (st == 0);
    } while (0);

    if (lc) layDestroy(lc);
    if (lb) layDestroy(lb);
    if (la) layDestroy(la);
    if (desc) descDestroy(desc);
    ltDestroy(h);
    return ok;
}

// ---------------- launch ----------------
extern "C" void kernel_launch(void* const* d_in, const int* in_sizes, int n_in,
                              void* d_out, int out_size) {
    const float* x   = (const float*)d_in[0];
    const float* mem = (const float*)d_in[1];
    float* out = (float*)d_out;

    prep_mem_kernel<<<C_ROWS, 256>>>(mem);
    prep_x_kernel<<<B_ROWS, 256>>>(x);

    if (run_cublas_gemm()) {
        scan_rescore_kernel<<<B_ROWS, 256>>>(x, mem, out);
    } else {
        cudaFuncSetAttribute(f_gemm_topk_kernel,
                             cudaFuncAttributeMaxDynamicSharedMemorySize, F_SMEM);
        f_gemm_topk_kernel<<<dim3(B_ROWS / FBM, F_NT), 256, F_SMEM>>>();
        f_rescore_out_kernel<<<B_ROWS, 256>>>(x, mem, out);
    }
}